// round 2
// baseline (speedup 1.0000x reference)
#include <cuda_runtime.h>
#include <cuda_bf16.h>

// DynamicFilter fused kernel, fp32 SIMT baseline using packed f32x2 FMA.
//
// out[b,c,h,w] = sum_p ( sum_k W[c*9+p,k]*x[b,k,h,w] + bias[c*9+p] ) * xpad[b,c,h+p/3-1,w+p%3-1]
//
// Grid: (channel_block=16, h=128, b=4). Block: 256 threads.
// Thread (tc,tw): output channel c = cb*16+tc, columns w = tw + 16*m, m=0..7.
// All 9 taps (p) of a channel are accumulated in-thread -> epilogue is local.

#define BN 4
#define CN 256
#define HN 128
#define WNX 128
#define KC 32
#define CB 16
#define ROWS (CB * 9)        // 144 contiguous W rows per channel block
#define WSTRIDE (KC + 1)     // 33: bank-conflict-free

__global__ __launch_bounds__(256, 2)
void dynfilter_kernel(const float* __restrict__ x,
                      const float* __restrict__ Wm,
                      const float* __restrict__ bias,
                      float* __restrict__ out)
{
    __shared__ float Wsh[ROWS * WSTRIDE];   // 144 x 33 floats = 19008 B
    __shared__ float Xsh[KC * WNX];         // 32 x 128 floats = 16384 B

    const int cb  = blockIdx.x;   // 0..15
    const int h   = blockIdx.y;   // 0..127
    const int bb  = blockIdx.z;   // 0..3

    const int tid = threadIdx.x;
    const int tc  = tid >> 4;     // 0..15  (channel within block)
    const int tw  = tid & 15;     // 0..15  (column phase)

    const int c = cb * CB + tc;   // output channel

    // 9 taps x 8 columns, packed as f32x2 pairs over column halves:
    // pair q holds columns w = tw+32q (lo) and w = tw+32q+16 (hi)
    unsigned long long acc[9][4];
#pragma unroll
    for (int p = 0; p < 9; ++p)
#pragma unroll
        for (int q = 0; q < 4; ++q) acc[p][q] = 0ULL;

    const float* Wblk = Wm + (size_t)cb * ROWS * CN;               // contiguous rows
    const float* xrow = x + (((size_t)bb * CN) * HN + h) * WNX;    // + k*HN*WNX

    for (int kc = 0; kc < CN; kc += KC) {
        __syncthreads();
        // stage W chunk: 144 rows x 32 k (each warp loads one 128B row segment)
#pragma unroll
        for (int i = tid; i < ROWS * KC; i += 256) {
            int rr = i >> 5, k = i & 31;
            Wsh[rr * WSTRIDE + k] = Wblk[(size_t)rr * CN + kc + k];
        }
        // stage X chunk: 32 channels x 128 w (fully coalesced rows)
#pragma unroll
        for (int i = tid; i < KC * WNX; i += 256) {
            int ch = i >> 7, w = i & 127;
            Xsh[ch * WNX + w] = xrow[(size_t)(kc + ch) * HN * WNX + w];
        }
        __syncthreads();

#pragma unroll 8
        for (int k = 0; k < KC; ++k) {
            // B operand: 8 columns packed into 4 f32x2
            unsigned long long b2[4];
#pragma unroll
            for (int q = 0; q < 4; ++q) {
                float b0 = Xsh[k * WNX + tw + 32 * q];
                float b1 = Xsh[k * WNX + tw + 32 * q + 16];
                asm("mov.b64 %0, {%1, %2};" : "=l"(b2[q]) : "f"(b0), "f"(b1));
            }
            // A operand: 9 filter rows for this channel (broadcast LDS)
#pragma unroll
            for (int p = 0; p < 9; ++p) {
                float av = Wsh[(tc * 9 + p) * WSTRIDE + k];
                unsigned long long a2;
                asm("mov.b64 %0, {%1, %1};" : "=l"(a2) : "f"(av));
#pragma unroll
                for (int q = 0; q < 4; ++q)
                    asm("fma.rn.f32x2 %0, %1, %2, %0;"
                        : "+l"(acc[p][q]) : "l"(a2), "l"(b2[q]));
            }
        }
    }

    // ---- epilogue: 9-tap dynamic filter contraction (register-local) ----
    float bp[9];
#pragma unroll
    for (int p = 0; p < 9; ++p) bp[p] = bias[c * 9 + p];

    const float* xc = x + ((size_t)bb * CN + c) * HN * WNX;

    float res[8];
#pragma unroll
    for (int m = 0; m < 8; ++m) res[m] = 0.f;

#pragma unroll
    for (int p = 0; p < 9; ++p) {
        const int di = p / 3 - 1;
        const int dj = p % 3 - 1;
        const int hh = h + di;
        const bool hok = (hh >= 0) && (hh < HN);
        const float* xr = xc + (size_t)hh * WNX;
#pragma unroll
        for (int q = 0; q < 4; ++q) {
            float f0, f1;
            asm("mov.b64 {%0, %1}, %2;" : "=f"(f0), "=f"(f1) : "l"(acc[p][q]));
            f0 += bp[p];
            f1 += bp[p];
            const int w0 = tw + 32 * q;
            const int w1 = w0 + 16;
            const int ww0 = w0 + dj;
            const int ww1 = w1 + dj;
            float xn0 = (hok && ww0 >= 0 && ww0 < WNX) ? __ldg(xr + ww0) : 0.f;
            float xn1 = (hok && ww1 >= 0 && ww1 < WNX) ? __ldg(xr + ww1) : 0.f;
            res[2 * q]     += f0 * xn0;
            res[2 * q + 1] += f1 * xn1;
        }
    }

    float* orow = out + (((size_t)bb * CN + c) * HN + h) * WNX;
#pragma unroll
    for (int q = 0; q < 4; ++q) {
        orow[tw + 32 * q]      = res[2 * q];
        orow[tw + 32 * q + 16] = res[2 * q + 1];
    }
}

extern "C" void kernel_launch(void* const* d_in, const int* in_sizes, int n_in,
                              void* d_out, int out_size)
{
    // Identify inputs by element count (robust to metadata ordering):
    // x: 4*256*128*128 = 16777216, W: 2304*256 = 589824, b: 2304
    const float* x = nullptr;
    const float* Wm = nullptr;
    const float* b = nullptr;
    for (int i = 0; i < n_in; ++i) {
        if (in_sizes[i] == 16777216)     x  = (const float*)d_in[i];
        else if (in_sizes[i] == 589824)  Wm = (const float*)d_in[i];
        else if (in_sizes[i] == 2304)    b  = (const float*)d_in[i];
    }
    float* out = (float*)d_out;

    dim3 grid(CN / CB, HN, BN);   // (16, 128, 4) = 8192 CTAs
    dynfilter_kernel<<<grid, 256>>>(x, Wm, b, out);
}

// round 9
// speedup vs baseline: 1.7726x; 1.7726x over previous
#include <cuda_runtime.h>
#include <cuda_bf16.h>
#include <cstdint>

// DynamicFilter via PTX mma.sync m16n8k8 tf32 + fused 9-tap epilogue.
// CTA=(h,b). X row (256k x 128w) resident in SMEM; W streamed via cp.async ring.
// W pre-permuted (wperm_kernel) so n = 8*tap+ch and k pair-swapped for v2 B loads.

#define CN 256
#define HN 128
#define WN 128
#define HW (HN*WN)

#define XROWB 544u                 // bytes per X smem row (136 floats)
#define XBYTES (256u*XROWB)        // 139264
#define WCHUNK 2592                // floats per W chunk (72 rows x 36)
#define WCHUNKB 10368u
#define SMEM_TOTAL (XBYTES + 4u*WCHUNKB)   // 180736

__device__ float g_wperm[256 * WCHUNK];    // [chunk][n][36]

#define CPA16(dst, src) \
    asm volatile("cp.async.cg.shared.global [%0], [%1], 16;" :: "r"(dst), "l"(src) : "memory")
#define CP_COMMIT() asm volatile("cp.async.commit_group;" ::: "memory")
#define CP_WAIT(n)  asm volatile("cp.async.wait_group %0;" :: "n"(n) : "memory")

__device__ __forceinline__ uint32_t smem_u32(const void* p){
    uint32_t a;
    asm("{ .reg .u64 t; cvta.to.shared.u64 t, %1; cvt.u32.u64 %0, t; }" : "=r"(a) : "l"(p));
    return a;
}

__device__ __forceinline__ void mma8(float* c, const uint32_t* a, uint32_t b0, uint32_t b1){
    asm volatile(
        "mma.sync.aligned.m16n8k8.row.col.f32.tf32.tf32.f32 "
        "{%0,%1,%2,%3}, {%4,%5,%6,%7}, {%8,%9}, {%0,%1,%2,%3};"
        : "+f"(c[0]), "+f"(c[1]), "+f"(c[2]), "+f"(c[3])
        : "r"(a[0]), "r"(a[1]), "r"(a[2]), "r"(a[3]), "r"(b0), "r"(b1));
}

// ---- pre-kernel: permute + tf32-round W into g_wperm ----
__global__ void wperm_kernel(const float* __restrict__ Wm){
    int idx = blockIdx.x * 256 + threadIdx.x;     // 2304*256 total
    if (idx >= 2304 * 256) return;
    int row = idx >> 8, k = idx & 255;
    int cb = row / 72, r = row % 72;
    int ch = r / 9, p = r % 9;
    int n  = 8 * p + ch;                          // lane-aligned channel remap
    int kc = k >> 5, kk = k & 31;
    int jj = kk >> 3, r8 = kk & 7;
    int col = 8 * jj + 2 * (r8 & 3) + (r8 >> 2);  // pair permutation for v2 loads
    uint32_t t; asm("cvt.rna.tf32.f32 %0, %1;" : "=r"(t) : "f"(Wm[idx]));
    g_wperm[(size_t)(cb * 8 + kc) * WCHUNK + n * 36 + col] = __uint_as_float(t);
}

extern __shared__ float smf[];

__device__ __forceinline__ void stage_w(int chunk, uint32_t sw, int tid){
    const uint32_t wd = sw + (uint32_t)(chunk & 3) * WCHUNKB;
    const float* wsrc = g_wperm + (size_t)chunk * WCHUNK;
    #pragma unroll
    for (int i = 0; i < 3; ++i) {
        int slot = tid + 256 * i;                 // 648 x 16B
        if (slot < 648) CPA16(wd + slot * 16, (const void*)(wsrc + slot * 4));
    }
    CP_COMMIT();
}

__global__ __launch_bounds__(256, 1)
void dynf_mma(const float* __restrict__ x, const float* __restrict__ bias,
              float* __restrict__ out)
{
    const uint32_t sx = smem_u32(smf);
    const uint32_t sw = sx + XBYTES;

    const int tid  = threadIdx.x;
    const int wid  = tid >> 5;
    const int lane = tid & 31;
    const int g = lane >> 2, q = lane & 3;
    const int h  = blockIdx.x;
    const int bb = blockIdx.y;
    const int wb = wid * 16;                      // warp's 16-row M strip

    // stage full X row: 256 k-rows x 32 float4 (one commit group)
    {
        const float* xsrc = x + (size_t)bb * CN * HW + (size_t)h * WN;
        #pragma unroll
        for (int i = 0; i < 32; ++i) {
            int slot = tid + 256 * i;
            int k = slot >> 5, w4 = slot & 31;
            CPA16(sx + (uint32_t)k * XROWB + (uint32_t)w4 * 16,
                  (const void*)(xsrc + (size_t)k * HW + w4 * 4));
        }
        CP_COMMIT();
    }
    stage_w(0, sw, tid);
    stage_w(1, sw, tid);

    for (int cb = 0; cb < 32; ++cb) {
        float acc[9][4];
        #pragma unroll
        for (int j = 0; j < 9; ++j)
            #pragma unroll
            for (int e = 0; e < 4; ++e) acc[j][e] = 0.f;

        for (int kc = 0; kc < 8; ++kc) {
            const int chunk = cb * 8 + kc;
            if (chunk + 2 < 256) stage_w(chunk + 2, sw, tid);
            if (chunk < 254) { CP_WAIT(2); } else { CP_WAIT(0); }
            __syncthreads();

            const uint32_t wbf = sw + (uint32_t)(chunk & 3) * WCHUNKB;
            #pragma unroll
            for (int jj = 0; jj < 4; ++jj) {
                // A fragment: rows wb+g, wb+g+8; k = kc*32+8jj+q, +4
                const uint32_t r0 = sx + (uint32_t)(kc * 32 + 8 * jj + q) * XROWB
                                  + (uint32_t)(wb + g) * 4;
                const uint32_t r1 = r0 + 4 * XROWB;
                float f0, f1, f2, f3;
                asm volatile("ld.shared.f32 %0, [%1];" : "=f"(f0) : "r"(r0));
                asm volatile("ld.shared.f32 %0, [%1];" : "=f"(f1) : "r"(r0 + 32));
                asm volatile("ld.shared.f32 %0, [%1];" : "=f"(f2) : "r"(r1));
                asm volatile("ld.shared.f32 %0, [%1];" : "=f"(f3) : "r"(r1 + 32));
                uint32_t a[4];
                asm("cvt.rna.tf32.f32 %0, %1;" : "=r"(a[0]) : "f"(f0));
                asm("cvt.rna.tf32.f32 %0, %1;" : "=r"(a[1]) : "f"(f1));
                asm("cvt.rna.tf32.f32 %0, %1;" : "=r"(a[2]) : "f"(f2));
                asm("cvt.rna.tf32.f32 %0, %1;" : "=r"(a[3]) : "f"(f3));
                #pragma unroll
                for (int j = 0; j < 9; ++j) {
                    uint32_t b0, b1;
                    const uint32_t baddr = wbf + (uint32_t)(8 * j + g) * 144u
                                         + (uint32_t)(jj * 32 + q * 8);
                    asm volatile("ld.shared.v2.b32 {%0,%1}, [%2];"
                                 : "=r"(b0), "=r"(b1) : "r"(baddr));
                    mma8(acc[j], a, b0, b1);
                }
            }
        }

        // fused 9-tap epilogue: lane (g,q) owns ch 2q,2q+1 at w = wb+g, wb+g+8
        #pragma unroll
        for (int b2 = 0; b2 < 2; ++b2) {
            const int ch = 2 * q + b2;
            const int c  = cb * 8 + ch;
            const float* xc = x + (size_t)(bb * CN + c) * HW;
            const float* bp = bias + cb * 72 + ch * 9;
            float res0 = 0.f, res1 = 0.f;
            const int w0 = wb + g, w1 = w0 + 8;
            #pragma unroll
            for (int j = 0; j < 9; ++j) {
                const int di = j / 3 - 1, dj = j % 3 - 1;
                const int hh = h + di;
                const bool hok = (hh >= 0) && (hh < HN);
                const float bv = __ldg(bp + j);
                const float* xr = xc + (size_t)hh * WN;
                const int ww0 = w0 + dj, ww1 = w1 + dj;
                const float fa = acc[j][b2]     + bv;   // row g
                const float fb = acc[j][2 + b2] + bv;   // row g+8
                const float xv0 = (hok && ww0 >= 0 && ww0 < WN) ? __ldg(xr + ww0) : 0.f;
                const float xv1 = (hok && ww1 >= 0 && ww1 < WN) ? __ldg(xr + ww1) : 0.f;
                res0 += fa * xv0;
                res1 += fb * xv1;
            }
            float* orow = out + (size_t)(bb * CN + c) * HW + (size_t)h * WN;
            orow[w0] = res0;
            orow[w1] = res1;
        }
    }
}

extern "C" void kernel_launch(void* const* d_in, const int* in_sizes, int n_in,
                              void* d_out, int out_size)
{
    const float* x = nullptr; const float* Wm = nullptr; const float* b = nullptr;
    for (int i = 0; i < n_in; ++i) {
        if      (in_sizes[i] == 16777216) x  = (const float*)d_in[i];
        else if (in_sizes[i] == 589824)   Wm = (const float*)d_in[i];
        else if (in_sizes[i] == 2304)     b  = (const float*)d_in[i];
    }
    float* out = (float*)d_out;

    wperm_kernel<<<2304, 256>>>(Wm);

    static int cfg_done = 0;
    if (!cfg_done) {
        cudaFuncSetAttribute(dynf_mma, cudaFuncAttributeMaxDynamicSharedMemorySize,
                             (int)SMEM_TOTAL);
        cfg_done = 1;
    }
    dim3 grid(HN, 4);                 // 512 CTAs: one per (h, b)
    dynf_mma<<<grid, 256, SMEM_TOTAL>>>(x, b, out);
}

// round 10
// speedup vs baseline: 2.8791x; 1.6242x over previous
#include <cuda_runtime.h>
#include <cuda_bf16.h>
#include <cstdint>

// DynamicFilter via PTX mma.sync m16n8k8 tf32 + fused 9-tap epilogue.
// CTA=(h,b), 8 warps in two independent halves. Each half: 4 warps x M=32,
// covers all M=128, processes 16 of the 32 cb tiles with its own W cp.async ring.
// X row staged once, tf32-converted in place. W pre-permuted by wperm_kernel.

#define CN 256
#define HN 128
#define WN 128
#define HW (HN*WN)

#define XROWB 544u                 // bytes per X smem row (136 floats)
#define XBYTES (256u*XROWB)        // 139264
#define WCHUNK 2592                // floats per W chunk (72 rows x 36)
#define WCHUNKB 10368u
#define SMEM_TOTAL (XBYTES + 8u*WCHUNKB)   // 139264 + 82944 = 222208

__device__ float g_wperm[256 * WCHUNK];    // [chunk][n][36]

#define CPA16(dst, src) \
    asm volatile("cp.async.cg.shared.global [%0], [%1], 16;" :: "r"(dst), "l"(src) : "memory")
#define CP_COMMIT() asm volatile("cp.async.commit_group;" ::: "memory")
#define CP_WAIT(n)  asm volatile("cp.async.wait_group %0;" :: "n"(n) : "memory")

__device__ __forceinline__ uint32_t smem_u32(const void* p){
    uint32_t a;
    asm("{ .reg .u64 t; cvta.to.shared.u64 t, %1; cvt.u32.u64 %0, t; }" : "=r"(a) : "l"(p));
    return a;
}

__device__ __forceinline__ void mma8(float* c, const uint32_t* a, uint32_t b0, uint32_t b1){
    asm volatile(
        "mma.sync.aligned.m16n8k8.row.col.f32.tf32.tf32.f32 "
        "{%0,%1,%2,%3}, {%4,%5,%6,%7}, {%8,%9}, {%0,%1,%2,%3};"
        : "+f"(c[0]), "+f"(c[1]), "+f"(c[2]), "+f"(c[3])
        : "r"(a[0]), "r"(a[1]), "r"(a[2]), "r"(a[3]), "r"(b0), "r"(b1));
}

// ---- pre-kernel: permute + tf32-round W into g_wperm ----
__global__ void wperm_kernel(const float* __restrict__ Wm){
    int idx = blockIdx.x * 256 + threadIdx.x;     // 2304*256 total
    if (idx >= 2304 * 256) return;
    int row = idx >> 8, k = idx & 255;
    int cb = row / 72, r = row % 72;
    int ch = r / 9, p = r % 9;
    int n  = 8 * p + ch;                          // lane-aligned channel remap
    int kc = k >> 5, kk = k & 31;
    int jj = kk >> 3, r8 = kk & 7;
    int col = 8 * jj + 2 * (r8 & 3) + (r8 >> 2);  // pair permutation for v2 loads
    uint32_t t; asm("cvt.rna.tf32.f32 %0, %1;" : "=r"(t) : "f"(Wm[idx]));
    g_wperm[(size_t)(cb * 8 + kc) * WCHUNK + n * 36 + col] = __uint_as_float(t);
}

extern __shared__ float smf[];

__device__ __forceinline__ void stage_wh(int chunk, uint32_t wd, int tidh){
    const float* wsrc = g_wperm + (size_t)chunk * WCHUNK;
    #pragma unroll
    for (int i = 0; i < 6; ++i) {
        int slot = tidh + 128 * i;                // 648 x 16B
        if (slot < 648) CPA16(wd + slot * 16, (const void*)(wsrc + slot * 4));
    }
    CP_COMMIT();
}

__global__ __launch_bounds__(256, 1)
void dynf_mma(const float* __restrict__ x, const float* __restrict__ bias,
              float* __restrict__ out)
{
    const uint32_t sx = smem_u32(smf);

    const int tid  = threadIdx.x;
    const int wid  = tid >> 5;
    const int lane = tid & 31;
    const int g = lane >> 2, q = lane & 3;
    const int half = wid >> 2;                    // 0: cb 0-15, 1: cb 16-31
    const int tidh = tid & 127;
    const int wb   = (wid & 3) * 32;              // warp's 32-row M strip
    const int h  = blockIdx.x;
    const int bb = blockIdx.y;

    const uint32_t swh = sx + XBYTES + (uint32_t)half * (4u * WCHUNKB);

    // stage full X row: 256 k-rows x 32 float4 (all 256 threads, one group)
    {
        const float* xsrc = x + (size_t)bb * CN * HW + (size_t)h * WN;
        #pragma unroll
        for (int i = 0; i < 32; ++i) {
            int slot = tid + 256 * i;
            int k = slot >> 5, w4 = slot & 31;
            CPA16(sx + (uint32_t)k * XROWB + (uint32_t)w4 * 16,
                  (const void*)(xsrc + (size_t)k * HW + w4 * 4));
        }
        CP_COMMIT();
    }
    // stage my half's first two W chunks (overlap with X arrival)
    stage_wh(half * 128 + 0, swh + 0 * WCHUNKB, tidh);
    stage_wh(half * 128 + 1, swh + 1 * WCHUNKB, tidh);

    CP_WAIT(0);
    __syncthreads();

    // in-place tf32 conversion of X (8704 float4 slots incl. padding)
    #pragma unroll 4
    for (int i = 0; i < 34; ++i) {
        uint32_t addr = sx + (uint32_t)(tid + 256 * i) * 16;
        uint32_t v0, v1, v2, v3;
        asm volatile("ld.shared.v4.b32 {%0,%1,%2,%3}, [%4];"
                     : "=r"(v0), "=r"(v1), "=r"(v2), "=r"(v3) : "r"(addr));
        asm("cvt.rna.tf32.f32 %0, %0;" : "+r"(v0));
        asm("cvt.rna.tf32.f32 %0, %0;" : "+r"(v1));
        asm("cvt.rna.tf32.f32 %0, %0;" : "+r"(v2));
        asm("cvt.rna.tf32.f32 %0, %0;" : "+r"(v3));
        asm volatile("st.shared.v4.b32 [%0], {%1,%2,%3,%4};"
                     :: "r"(addr), "r"(v0), "r"(v1), "r"(v2), "r"(v3) : "memory");
    }
    __syncthreads();

    // ===== per-half main loop: 16 cb tiles, 8 k-chunks each =====
    for (int cbl = 0; cbl < 16; ++cbl) {
        const int cb = half * 16 + cbl;
        float acc[9][2][4];
        #pragma unroll
        for (int j = 0; j < 9; ++j)
            #pragma unroll
            for (int s = 0; s < 2; ++s)
                #pragma unroll
                for (int e = 0; e < 4; ++e) acc[j][s][e] = 0.f;

        for (int kc = 0; kc < 8; ++kc) {
            const int i = cbl * 8 + kc;
            if (i + 2 < 128)
                stage_wh(half * 128 + i + 2, swh + (uint32_t)((i + 2) & 3) * WCHUNKB, tidh);
            if (i < 126)      { CP_WAIT(2); }
            else if (i == 126){ CP_WAIT(1); }
            else              { CP_WAIT(0); }
            if (half == 0) asm volatile("bar.sync 1, 128;" ::: "memory");
            else           asm volatile("bar.sync 2, 128;" ::: "memory");

            const uint32_t wbf = swh + (uint32_t)(i & 3) * WCHUNKB;
            #pragma unroll
            for (int jj = 0; jj < 4; ++jj) {
                // A fragments (already tf32): strips wb and wb+16
                const uint32_t r0 = sx + (uint32_t)(kc * 32 + 8 * jj + q) * XROWB
                                  + (uint32_t)(wb + g) * 4;
                uint32_t a0[4], a1[4];
                asm volatile("ld.shared.b32 %0, [%1];"       : "=r"(a0[0]) : "r"(r0));
                asm volatile("ld.shared.b32 %0, [%1+32];"    : "=r"(a0[1]) : "r"(r0));
                asm volatile("ld.shared.b32 %0, [%1+2176];"  : "=r"(a0[2]) : "r"(r0)); // +4 rows
                asm volatile("ld.shared.b32 %0, [%1+2208];"  : "=r"(a0[3]) : "r"(r0));
                asm volatile("ld.shared.b32 %0, [%1+64];"    : "=r"(a1[0]) : "r"(r0));
                asm volatile("ld.shared.b32 %0, [%1+96];"    : "=r"(a1[1]) : "r"(r0));
                asm volatile("ld.shared.b32 %0, [%1+2240];"  : "=r"(a1[2]) : "r"(r0));
                asm volatile("ld.shared.b32 %0, [%1+2272];"  : "=r"(a1[3]) : "r"(r0));
                #pragma unroll
                for (int j = 0; j < 9; ++j) {
                    uint32_t b0, b1;
                    const uint32_t baddr = wbf + (uint32_t)(8 * j + g) * 144u
                                         + (uint32_t)(jj * 32 + q * 8);
                    asm volatile("ld.shared.v2.b32 {%0,%1}, [%2];"
                                 : "=r"(b0), "=r"(b1) : "r"(baddr));
                    mma8(acc[j][0], a0, b0, b1);
                    mma8(acc[j][1], a1, b0, b1);
                }
            }
        }

        // ---- fused 9-tap epilogue: lane (g,q) owns ch 2q,2q+1 at 4 w positions ----
        #pragma unroll
        for (int b2 = 0; b2 < 2; ++b2) {
            const int ch = 2 * q + b2;
            const int c  = cb * 8 + ch;
            const float* xc = x + (size_t)(bb * CN + c) * HW;
            const float* bp = bias + cb * 72 + ch * 9;
            float res[4] = {0.f, 0.f, 0.f, 0.f};
            const int wpos[4] = { wb + g, wb + g + 8, wb + 16 + g, wb + 24 + g };
            #pragma unroll
            for (int j = 0; j < 9; ++j) {
                const int di = j / 3 - 1, dj = j % 3 - 1;
                const int hh = h + di;
                const bool hok = (hh >= 0) && (hh < HN);
                const float bv = __ldg(bp + j);
                const float* xr = xc + (size_t)hh * WN;
                const float fv[4] = { acc[j][0][b2],     acc[j][0][2 + b2],
                                      acc[j][1][b2],     acc[j][1][2 + b2] };
                #pragma unroll
                for (int r = 0; r < 4; ++r) {
                    const int ww = wpos[r] + dj;
                    const float xv = (hok && ww >= 0 && ww < WN) ? __ldg(xr + ww) : 0.f;
                    res[r] += (fv[r] + bv) * xv;
                }
            }
            float* orow = out + (size_t)(bb * CN + c) * HW + (size_t)h * WN;
            #pragma unroll
            for (int r = 0; r < 4; ++r) orow[wpos[r]] = res[r];
        }
    }
}

extern "C" void kernel_launch(void* const* d_in, const int* in_sizes, int n_in,
                              void* d_out, int out_size)
{
    const float* x = nullptr; const float* Wm = nullptr; const float* b = nullptr;
    for (int i = 0; i < n_in; ++i) {
        if      (in_sizes[i] == 16777216) x  = (const float*)d_in[i];
        else if (in_sizes[i] == 589824)   Wm = (const float*)d_in[i];
        else if (in_sizes[i] == 2304)     b  = (const float*)d_in[i];
    }
    float* out = (float*)d_out;

    wperm_kernel<<<2304, 256>>>(Wm);

    static int cfg_done = 0;
    if (!cfg_done) {
        cudaFuncSetAttribute(dynf_mma, cudaFuncAttributeMaxDynamicSharedMemorySize,
                             (int)SMEM_TOTAL);
        cfg_done = 1;
    }
    dim3 grid(HN, 4);                 // 512 CTAs: one per (h, b)
    dynf_mma<<<grid, 256, SMEM_TOTAL>>>(x, b, out);
}

// round 11
// speedup vs baseline: 5.5323x; 1.9216x over previous
#include <cuda_runtime.h>
#include <cuda_fp16.h>
#include <cstdint>

// DynamicFilter via PTX mma.sync m16n8k16 fp16 (f32 accum) + fused 9-tap epilogue.
// CTA=(h,b), 8 warps in two halves; each half: 4 warps x M=32, 16 of 32 cb tiles,
// own cp.async W ring. X row staged once as packed f16x2 k-pairs. W pre-permuted.

#define CN 256
#define HN 128
#define WN 128
#define HW (HN*WN)

#define XPROWB 544u                 // bytes per packed-X row (128 b32 + pad), stride%128=32
#define XPBYTES (128u*XPROWB)       // 69632 (128 k-pair rows)
#define WROWB 160u                  // bytes per W n-row in a chunk (4 steps x 32B + pad)
#define WCHUNKB (72u*WROWB)         // 11520 per k64 chunk
#define SMEM_TOTAL (XPBYTES + 8u*WCHUNKB)   // 69632 + 92160 = 161792

__device__ uint32_t g_wperm[32 * 4 * 72 * 40];   // [cb][cc][n][40 words]

#define CPA16(dst, src) \
    asm volatile("cp.async.cg.shared.global [%0], [%1], 16;" :: "r"(dst), "l"(src) : "memory")
#define CP_COMMIT() asm volatile("cp.async.commit_group;" ::: "memory")
#define CP_WAIT(n)  asm volatile("cp.async.wait_group %0;" :: "n"(n) : "memory")

__device__ __forceinline__ uint32_t smem_u32(const void* p){
    uint32_t a;
    asm("{ .reg .u64 t; cvta.to.shared.u64 t, %1; cvt.u32.u64 %0, t; }" : "=r"(a) : "l"(p));
    return a;
}

__device__ __forceinline__ uint32_t pack_h2(float lo, float hi){
    uint32_t d;
    asm("cvt.rn.f16x2.f32 %0, %1, %2;" : "=r"(d) : "f"(hi), "f"(lo));  // %1->hi, %2->lo
    return d;
}

__device__ __forceinline__ void mma16(float* c, const uint32_t* a, uint32_t b0, uint32_t b1){
    asm volatile(
        "mma.sync.aligned.m16n8k16.row.col.f32.f16.f16.f32 "
        "{%0,%1,%2,%3}, {%4,%5,%6,%7}, {%8,%9}, {%0,%1,%2,%3};"
        : "+f"(c[0]), "+f"(c[1]), "+f"(c[2]), "+f"(c[3])
        : "r"(a[0]), "r"(a[1]), "r"(a[2]), "r"(a[3]), "r"(b0), "r"(b1));
}

// ---- pre-kernel: permute + fp16-pack W into g_wperm ----
// thread per (row, kpair): n = 8*tap+ch remap; k-pairs permuted for v2 B loads.
__global__ void wperm_kernel(const float* __restrict__ Wm){
    int idx = blockIdx.x * 256 + threadIdx.x;        // 2304 * 128 total
    if (idx >= 2304 * 128) return;
    int row = idx >> 7, kp = idx & 127;
    int cb = row / 72, r = row % 72;
    int ch = r / 9, p = r % 9;
    int n  = 8 * p + ch;                             // lane-aligned channel remap
    int cc = kp >> 5, kpl = kp & 31;
    int s = kpl >> 3, kp8 = kpl & 7;
    int col = 2 * (kp8 & 3) + (kp8 >> 2);            // (b0,b1) = pairs (q, q+4)
    float e = Wm[row * 256 + 2 * kp];
    float o = Wm[row * 256 + 2 * kp + 1];
    g_wperm[((size_t)(cb * 4 + cc) * 72 + n) * 40 + s * 8 + col] = pack_h2(e, o);
}

extern __shared__ float smf[];

__device__ __forceinline__ void stage_wh(int chunk, uint32_t wd, int tidh){
    const uint32_t* wsrc = g_wperm + (size_t)chunk * (72 * 40);
    #pragma unroll
    for (int i = 0; i < 6; ++i) {
        int slot = tidh + 128 * i;                   // 720 x 16B
        if (slot < 720) CPA16(wd + slot * 16, (const void*)(wsrc + slot * 4));
    }
    CP_COMMIT();
}

__global__ __launch_bounds__(256, 1)
void dynf_mma(const float* __restrict__ x, const float* __restrict__ bias,
              float* __restrict__ out)
{
    const uint32_t sx = smem_u32(smf);

    const int tid  = threadIdx.x;
    const int wid  = tid >> 5;
    const int lane = tid & 31;
    const int g = lane >> 2, q = lane & 3;
    const int half = wid >> 2;                       // 0: cb 0-15, 1: cb 16-31
    const int tidh = tid & 127;
    const int wb   = (wid & 3) * 32;                 // warp's 32-row M strip
    const int h  = blockIdx.x;
    const int bb = blockIdx.y;

    const uint32_t swh = sx + XPBYTES + (uint32_t)half * (4u * WCHUNKB);

    // prefetch my half's first two W chunks
    stage_wh(half * 64 + 0, swh + 0 * WCHUNKB, tidh);
    stage_wh(half * 64 + 1, swh + 1 * WCHUNKB, tidh);

    // stage X row as packed f16x2 pairs: Xp[kp][w] = (x[2kp][w], x[2kp+1][w])
    {
        const float* xsrc = x + (size_t)bb * CN * HW + (size_t)h * WN;
        #pragma unroll 4
        for (int i = 0; i < 16; ++i) {
            int slot = tid + 256 * i;                // 4096: kp(128) x w4(32)
            int kp = slot >> 5, w4 = slot & 31;
            const float4 e = *(const float4*)(xsrc + (size_t)(2 * kp) * HW + w4 * 4);
            const float4 o = *(const float4*)(xsrc + (size_t)(2 * kp + 1) * HW + w4 * 4);
            uint32_t v0 = pack_h2(e.x, o.x), v1 = pack_h2(e.y, o.y);
            uint32_t v2 = pack_h2(e.z, o.z), v3 = pack_h2(e.w, o.w);
            asm volatile("st.shared.v4.b32 [%0], {%1,%2,%3,%4};"
                         :: "r"(sx + (uint32_t)kp * XPROWB + (uint32_t)w4 * 16),
                            "r"(v0), "r"(v1), "r"(v2), "r"(v3) : "memory");
        }
    }
    __syncthreads();

    // ===== per-half main loop: 16 cb tiles x 4 k64 chunks x 4 k16 steps =====
    for (int cbl = 0; cbl < 16; ++cbl) {
        const int cb = half * 16 + cbl;
        float acc[9][2][4];
        #pragma unroll
        for (int j = 0; j < 9; ++j)
            #pragma unroll
            for (int sA = 0; sA < 2; ++sA)
                #pragma unroll
                for (int e = 0; e < 4; ++e) acc[j][sA][e] = 0.f;

        for (int cc = 0; cc < 4; ++cc) {
            const int ci = cbl * 4 + cc;             // 0..63 per half
            if (ci + 2 < 64)
                stage_wh(half * 64 + ci + 2, swh + (uint32_t)((ci + 2) & 3) * WCHUNKB, tidh);
            if (ci < 62)      { CP_WAIT(2); }
            else if (ci == 62){ CP_WAIT(1); }
            else              { CP_WAIT(0); }
            if (half == 0) asm volatile("bar.sync 1, 128;" ::: "memory");
            else           asm volatile("bar.sync 2, 128;" ::: "memory");

            const uint32_t wbf = swh + (uint32_t)(ci & 3) * WCHUNKB;
            #pragma unroll
            for (int s = 0; s < 4; ++s) {            // k16 steps
                // A fragments (f16x2 pairs): kp = cc*32 + s*8 + q (+4), w strips
                const uint32_t r0 = sx + (uint32_t)(cc * 32 + s * 8 + q) * XPROWB
                                  + (uint32_t)(wb + g) * 4;
                uint32_t a0[4], a1[4];
                asm volatile("ld.shared.b32 %0, [%1];"      : "=r"(a0[0]) : "r"(r0));
                asm volatile("ld.shared.b32 %0, [%1+32];"   : "=r"(a0[1]) : "r"(r0));
                asm volatile("ld.shared.b32 %0, [%1+2176];" : "=r"(a0[2]) : "r"(r0)); // kp+4
                asm volatile("ld.shared.b32 %0, [%1+2208];" : "=r"(a0[3]) : "r"(r0));
                asm volatile("ld.shared.b32 %0, [%1+64];"   : "=r"(a1[0]) : "r"(r0));
                asm volatile("ld.shared.b32 %0, [%1+96];"   : "=r"(a1[1]) : "r"(r0));
                asm volatile("ld.shared.b32 %0, [%1+2240];" : "=r"(a1[2]) : "r"(r0));
                asm volatile("ld.shared.b32 %0, [%1+2272];" : "=r"(a1[3]) : "r"(r0));
                #pragma unroll
                for (int j = 0; j < 9; ++j) {
                    uint32_t b0, b1;
                    const uint32_t baddr = wbf + (uint32_t)(8 * j + g) * WROWB
                                         + (uint32_t)(s * 32 + q * 8);
                    asm volatile("ld.shared.v2.b32 {%0,%1}, [%2];"
                                 : "=r"(b0), "=r"(b1) : "r"(baddr));
                    mma16(acc[j][0], a0, b0, b1);
                    mma16(acc[j][1], a1, b0, b1);
                }
            }
        }

        // ---- fused 9-tap epilogue: lane (g,q) owns ch 2q,2q+1 at 4 w positions ----
        #pragma unroll
        for (int b2 = 0; b2 < 2; ++b2) {
            const int ch = 2 * q + b2;
            const int c  = cb * 8 + ch;
            const float* xc = x + (size_t)(bb * CN + c) * HW;
            const float* bp = bias + cb * 72 + ch * 9;
            float res[4] = {0.f, 0.f, 0.f, 0.f};
            const int wpos[4] = { wb + g, wb + g + 8, wb + 16 + g, wb + 24 + g };
            #pragma unroll
            for (int j = 0; j < 9; ++j) {
                const int di = j / 3 - 1, dj = j % 3 - 1;
                const int hh = h + di;
                const bool hok = (hh >= 0) && (hh < HN);
                const float bv = __ldg(bp + j);
                const float* xr = xc + (size_t)hh * WN;
                const float fv[4] = { acc[j][0][b2], acc[j][0][2 + b2],
                                      acc[j][1][b2], acc[j][1][2 + b2] };
                #pragma unroll
                for (int r = 0; r < 4; ++r) {
                    const int ww = wpos[r] + dj;
                    const float xv = (hok && ww >= 0 && ww < WN) ? __ldg(xr + ww) : 0.f;
                    res[r] += (fv[r] + bv) * xv;
                }
            }
            float* orow = out + (size_t)(bb * CN + c) * HW + (size_t)h * WN;
            #pragma unroll
            for (int r = 0; r < 4; ++r) orow[wpos[r]] = res[r];
        }
    }
}

extern "C" void kernel_launch(void* const* d_in, const int* in_sizes, int n_in,
                              void* d_out, int out_size)
{
    const float* x = nullptr; const float* Wm = nullptr; const float* b = nullptr;
    for (int i = 0; i < n_in; ++i) {
        if      (in_sizes[i] == 16777216) x  = (const float*)d_in[i];
        else if (in_sizes[i] == 589824)   Wm = (const float*)d_in[i];
        else if (in_sizes[i] == 2304)     b  = (const float*)d_in[i];
    }
    float* out = (float*)d_out;

    wperm_kernel<<<1152, 256>>>(Wm);

    static int cfg_done = 0;
    if (!cfg_done) {
        cudaFuncSetAttribute(dynf_mma, cudaFuncAttributeMaxDynamicSharedMemorySize,
                             (int)SMEM_TOTAL);
        cfg_done = 1;
    }
    dim3 grid(HN, 4);                 // 512 CTAs: one per (h, b)
    dynf_mma<<<grid, 256, SMEM_TOTAL>>>(x, b, out);
}